// round 5
// baseline (speedup 1.0000x reference)
#include <cuda_runtime.h>
#include <math.h>

#define B_     256
#define T_     1024
#define DIN    32
#define DH     200
#define DOUT   2
#define CHUNK  16
#define NCHUNK (T_ / CHUNK)
#define NTHR   256
#define PSTRIDE 201   // padded row stride (in float2) for partials -> conflict-light

__device__ __forceinline__ unsigned sm_u32(const void* p) {
    return (unsigned)__cvta_generic_to_shared(p);
}
__device__ __forceinline__ void cp16(unsigned saddr, const void* g) {
    asm volatile("cp.async.ca.shared.global [%0], [%1], 16;" :: "r"(saddr), "l"(g));
}
__device__ __forceinline__ unsigned long long pack2(float x, float y) {
    unsigned long long v;
    asm("mov.b64 %0, {%1, %2};" : "=l"(v) : "f"(x), "f"(y));
    return v;
}
__device__ __forceinline__ void fma2(unsigned long long& d,
                                     unsigned long long a, unsigned long long b) {
    asm("fma.rn.f32x2 %0, %1, %2, %0;" : "+l"(d) : "l"(a), "l"(b));
}

__global__ __launch_bounds__(NTHR, 2)
void snn_kernel(const float* __restrict__ x,  const float* __restrict__ W1,
                const float* __restrict__ b1, const float* __restrict__ W2,
                const float* __restrict__ b2, float* __restrict__ out,
                float a1, float a2)
{
    __shared__ __align__(16) float  xs[2][CHUNK * DIN];   // 4 KB double-buffered x
    __shared__ float2 part[CHUNK * PSTRIDE];              // layer-2 partials, ~25.7 KB
    __shared__ float  rbuf[CHUNK * DOUT];                 // reduced drives

    const int b   = blockIdx.x;
    const int tid = threadIdx.x;
    const bool lactive = (tid < DH);

    // output layout: output[B,2] | s1s[B,T,DH] | m1s[B,T,DH] | s2s[B,T,2] | m2s[B,T,2]
    float* out_o  = out;
    float* out_s1 = out + (size_t)B_ * DOUT;
    float* out_m1 = out_s1 + (size_t)B_ * T_ * DH;
    float* out_s2 = out_m1 + (size_t)B_ * T_ * DH;
    float* out_m2 = out_s2 + (size_t)B_ * T_ * DOUT;

    const float* xrow = x + (size_t)b * T_ * DIN;
    float* s1p = out_s1 + (size_t)b * T_ * DH;
    float* m1p = out_m1 + (size_t)b * T_ * DH;
    float* s2p = out_s2 + (size_t)b * T_ * DOUT;
    float* m2p = out_m2 + (size_t)b * T_ * DOUT;

    // ---- per-thread weights: W1 column packed over k-pairs (f32x2) ----
    unsigned long long wp[DIN / 2];
    float w20 = 0.f, w21 = 0.f;
    unsigned long long accInit = 0;
    if (lactive) {
        #pragma unroll
        for (int kk = 0; kk < DIN / 2; kk++)
            wp[kk] = pack2(W1[(2 * kk) * DH + tid], W1[(2 * kk + 1) * DH + tid]);
        w20 = W2[tid * 2 + 0];
        w21 = W2[tid * 2 + 1];
        accInit = pack2(b1[tid], 0.f);   // fold bias into dot accumulator
    }
    const float b2c = (tid < DOUT) ? b2[tid] : 0.f;

    float m1 = 0.f, m2 = 0.f, osum = 0.f;

    // ---- prefetch chunk 0 (2048 B = 128 x 16 B) ----
    if (tid < 128)
        cp16(sm_u32(&xs[0][tid * 4]), xrow + tid * 4);
    asm volatile("cp.async.commit_group;");

    for (int ch = 0; ch < NCHUNK; ch++) {
        const int buf = ch & 1;
        if (ch + 1 < NCHUNK) {
            if (tid < 128)
                cp16(sm_u32(&xs[buf ^ 1][tid * 4]),
                     xrow + (size_t)(ch + 1) * CHUNK * DIN + tid * 4);
            asm volatile("cp.async.commit_group;");
            asm volatile("cp.async.wait_group 1;");
        } else {
            asm volatile("cp.async.wait_group 0;");
        }
        __syncthreads();

        // ---- layer 1: 16 timesteps, packed f32x2 dot + spike + soft reset ----
        if (lactive) {
            const unsigned xbase = sm_u32(&xs[buf][0]);
            #pragma unroll 2
            for (int tt = 0; tt < CHUNK; tt++) {
                unsigned long long acc = accInit;
                const unsigned a0 = xbase + tt * (DIN * 4);
                #pragma unroll
                for (int q = 0; q < DIN / 4; q++) {
                    unsigned long long xa, xbv;
                    asm("ld.shared.v2.b64 {%0, %1}, [%2];"
                        : "=l"(xa), "=l"(xbv) : "r"(a0 + q * 16));
                    fma2(acc, xa,  wp[2 * q]);
                    fma2(acc, xbv, wp[2 * q + 1]);
                }
                float lo, hi;
                asm("mov.b64 {%0, %1}, %2;" : "=f"(lo), "=f"(hi) : "l"(acc));
                const float drive = lo + hi;
                m1 = fmaf(m1, a1, drive);
                const float s1 = (m1 > 0.5f) ? 1.0f : 0.0f;
                m1 -= s1 * 0.5f;                     // soft reset
                const int gt = ch * CHUNK + tt;
                s1p[(size_t)gt * DH + tid] = s1;
                m1p[(size_t)gt * DH + tid] = m1;
                part[tt * PSTRIDE + tid] = make_float2(s1 * w20, s1 * w21);
            }
        }
        __syncthreads();

        // ---- layer-2 drive reduction: 256 thr = 32 (t,c) pairs x 8 strands ----
        {
            const int p = tid >> 3;          // (t,c) pair index, 0..31
            const int u = tid & 7;           // strand
            const int tt = p >> 1, c = p & 1;
            const float* pp = (const float*)part;
            float s = 0.f;
            #pragma unroll 5
            for (int jj = 0; jj < 25; jj++) {
                const int j = u * 25 + jj;
                s += pp[(tt * PSTRIDE + j) * 2 + c];
            }
            s += __shfl_down_sync(0xffffffffu, s, 4, 8);
            s += __shfl_down_sync(0xffffffffu, s, 2, 8);
            s += __shfl_down_sync(0xffffffffu, s, 1, 8);
            if (u == 0) rbuf[p] = s;         // rbuf[tt*2 + c]
        }
        __syncthreads();

        // ---- layer-2 serial recurrence (2 threads, 16 steps) ----
        if (tid < DOUT) {
            const int c = tid;
            float mm = m2, os = osum;
            #pragma unroll
            for (int tt = 0; tt < CHUNK; tt++) {
                mm = fmaf(mm, a2, rbuf[tt * 2 + c] + b2c);
                const float s2 = (mm > 1.0f) ? 1.0f : 0.0f;
                mm -= s2;                    // soft reset (thresh2 = 1.0)
                const int gt = ch * CHUNK + tt;
                s2p[(size_t)gt * DOUT + c] = s2;
                m2p[(size_t)gt * DOUT + c] = mm;
                if (gt > 0) os += mm;
            }
            m2 = mm; osum = os;
        }
        __syncthreads();   // protect part/rbuf/x-buffer reuse
    }

    if (tid < DOUT)
        out_o[b * DOUT + tid] = osum * (1.0f / (float)T_);
}

extern "C" void kernel_launch(void* const* d_in, const int* in_sizes, int n_in,
                              void* d_out, int out_size) {
    const float* x  = (const float*)d_in[0];
    const float* W1 = (const float*)d_in[1];
    const float* b1 = (const float*)d_in[2];
    const float* W2 = (const float*)d_in[3];
    const float* b2 = (const float*)d_in[4];

    const float a1 = (float)exp((double)(-1.0f / 10.0f));
    const float a2 = (float)exp((double)(-1.0f / 20.0f));

    snn_kernel<<<B_, NTHR>>>(x, W1, b1, W2, b2, (float*)d_out, a1, a2);
}

// round 6
// speedup vs baseline: 1.1639x; 1.1639x over previous
#include <cuda_runtime.h>
#include <math.h>

#define B_     256
#define T_     1024
#define DIN    32
#define DH     200
#define DOUT   2
#define CHUNK  16
#define NCHUNK (T_ / CHUNK)
#define NTHR   256
#define NPROD  224          // warps 0..6 = producers; warp 7 = consumer
#define PAD2   201          // float2 row stride for partials (conflict-free)

#define XS_BYTES  (CHUNK * DIN * 4)          // 2048 per slot, 3 slots
#define PART_F2   (CHUNK * PAD2)             // 3216 float2 per buffer
#define OFF_XS    0
#define OFF_PART  (3 * XS_BYTES)                      // 6144
#define OFF_MBAR  (OFF_PART + 2 * PART_F2 * 8)        // 57600
#define SMEM_TOTAL (OFF_MBAR + 64)

__device__ __forceinline__ unsigned sm_u32(const void* p) {
    return (unsigned)__cvta_generic_to_shared(p);
}
__device__ __forceinline__ void cp16(unsigned saddr, const void* g) {
    asm volatile("cp.async.ca.shared.global [%0], [%1], 16;" :: "r"(saddr), "l"(g));
}
__device__ __forceinline__ unsigned long long pack2(float x, float y) {
    unsigned long long v;
    asm("mov.b64 %0, {%1, %2};" : "=l"(v) : "f"(x), "f"(y));
    return v;
}
__device__ __forceinline__ void fma2(unsigned long long& d,
                                     unsigned long long a, unsigned long long b) {
    asm("fma.rn.f32x2 %0, %1, %2, %0;" : "+l"(d) : "l"(a), "l"(b));
}
__device__ __forceinline__ void mbar_init(unsigned a, unsigned cnt) {
    asm volatile("mbarrier.init.shared.b64 [%0], %1;" :: "r"(a), "r"(cnt));
}
__device__ __forceinline__ void mbar_arrive(unsigned a) {
    asm volatile("mbarrier.arrive.shared.b64 _, [%0];" :: "r"(a) : "memory");
}
__device__ __forceinline__ void mbar_wait(unsigned a, unsigned parity) {
    asm volatile(
        "{\n\t.reg .pred P;\n\t"
        "WL_%=:\n\t"
        "mbarrier.try_wait.parity.acquire.cta.shared::cta.b64 P, [%0], %1, 0x989680;\n\t"
        "@P bra.uni WD_%=;\n\t"
        "bra.uni WL_%=;\n\t"
        "WD_%=:\n\t}"
        :: "r"(a), "r"(parity) : "memory");
}

__global__ __launch_bounds__(NTHR, 2)
void snn_kernel(const float* __restrict__ x,  const float* __restrict__ W1,
                const float* __restrict__ b1, const float* __restrict__ W2,
                const float* __restrict__ b2, float* __restrict__ out,
                float a1, float a2)
{
    extern __shared__ __align__(16) unsigned char smem_raw[];
    float2* part = (float2*)(smem_raw + OFF_PART);
    const unsigned smem_base = sm_u32(smem_raw);
    const unsigned xs_sa  = smem_base + OFF_XS;
    const unsigned mbF0 = smem_base + OFF_MBAR;       // full[0]
    const unsigned mbF1 = mbF0 + 8;                   // full[1]
    const unsigned mbE0 = mbF0 + 16;                  // empty[0]
    const unsigned mbE1 = mbF0 + 24;                  // empty[1]

    const int b   = blockIdx.x;
    const int tid = threadIdx.x;

    // output layout: output[B,2] | s1s[B,T,DH] | m1s[B,T,DH] | s2s[B,T,2] | m2s[B,T,2]
    float* out_o  = out;
    float* out_s1 = out + (size_t)B_ * DOUT;
    float* out_m1 = out_s1 + (size_t)B_ * T_ * DH;
    float* out_s2 = out_m1 + (size_t)B_ * T_ * DH;
    float* out_m2 = out_s2 + (size_t)B_ * T_ * DOUT;

    const float* xrow = x + (size_t)b * T_ * DIN;
    float* s1p = out_s1 + (size_t)b * T_ * DH;
    float* m1p = out_m1 + (size_t)b * T_ * DH;
    float* s2p = out_s2 + (size_t)b * T_ * DOUT;
    float* m2p = out_m2 + (size_t)b * T_ * DOUT;

    if (tid == 0) {
        mbar_init(mbF0, NPROD); mbar_init(mbF1, NPROD);
        mbar_init(mbE0, 32);    mbar_init(mbE1, 32);
    }

    // producer-side weights
    unsigned long long wp[DIN / 2];
    float w20 = 0.f, w21 = 0.f;
    unsigned long long accInit = 0;
    const unsigned long long zero64 = pack2(0.f, 0.f);
    if (tid < DH) {
        #pragma unroll
        for (int kk = 0; kk < DIN / 2; kk++)
            wp[kk] = pack2(W1[(2 * kk) * DH + tid], W1[(2 * kk + 1) * DH + tid]);
        w20 = W2[tid * 2 + 0];
        w21 = W2[tid * 2 + 1];
        accInit = pack2(b1[tid], 0.f);
    }
    __syncthreads();   // publish mbarrier init

    if (tid < NPROD) {
        // ================= PRODUCERS (layer 1) =================
        if (tid < 128) cp16(xs_sa + 0 * XS_BYTES + tid * 16, xrow + tid * 4);
        asm volatile("cp.async.commit_group;");
        if (tid < 128) cp16(xs_sa + 1 * XS_BYTES + tid * 16, xrow + CHUNK * DIN + tid * 4);
        asm volatile("cp.async.commit_group;");

        float m1 = 0.f;
        const bool lact = (tid < DH);

        for (int ch = 0; ch < NCHUNK; ch++) {
            asm volatile("cp.async.wait_group 1;");   // slot ch%3 complete (this thread)
            asm volatile("bar.sync 5, 224;" ::: "memory");  // publish + retire reads of ch-1

            if (ch + 2 < NCHUNK && tid < 128)
                cp16(xs_sa + ((ch + 2) % 3) * XS_BYTES + tid * 16,
                     xrow + (size_t)(ch + 2) * CHUNK * DIN + tid * 4);
            asm volatile("cp.async.commit_group;");

            const int buf = ch & 1;
            const int u   = ch >> 1;
            if (ch >= 2)
                mbar_wait(buf ? mbE1 : mbE0, (unsigned)((u & 1) ^ 1));

            if (lact) {
                const unsigned xbase = xs_sa + (ch % 3) * XS_BYTES;
                float*  pS = s1p + (size_t)ch * CHUNK * DH + tid;
                float*  pM = m1p + (size_t)ch * CHUNK * DH + tid;
                float2* pP = part + (size_t)buf * PART_F2 + tid;
                #pragma unroll 4
                for (int tt = 0; tt < CHUNK; tt++) {
                    unsigned long long acc0 = accInit, acc1 = zero64;
                    const unsigned a0 = xbase + tt * (DIN * 4);
                    #pragma unroll
                    for (int q = 0; q < DIN / 4; q++) {
                        unsigned long long xa, xbv;
                        asm("ld.shared.v2.b64 {%0, %1}, [%2];"
                            : "=l"(xa), "=l"(xbv) : "r"(a0 + q * 16));
                        fma2(acc0, xa,  wp[2 * q]);
                        fma2(acc1, xbv, wp[2 * q + 1]);
                    }
                    unsigned long long accs;
                    asm("add.rn.f32x2 %0, %1, %2;" : "=l"(accs) : "l"(acc0), "l"(acc1));
                    float lo, hi;
                    asm("mov.b64 {%0, %1}, %2;" : "=f"(lo), "=f"(hi) : "l"(accs));
                    m1 = fmaf(m1, a1, lo + hi);
                    const float s1 = (m1 > 0.5f) ? 1.0f : 0.0f;
                    m1 = fmaf(s1, -0.5f, m1);     // soft reset
                    *pS = s1;  pS += DH;
                    *pM = m1;  pM += DH;
                    *pP = make_float2(s1 * w20, s1 * w21);
                    pP += PAD2;
                }
            }
            mbar_arrive(buf ? mbF1 : mbF0);
        }
    } else {
        // ================= CONSUMER (layer 2) =================
        const int lane = tid & 31;
        const int tt   = lane >> 1;
        const int c    = lane & 1;
        const float b2c = b2[c];
        float m2 = 0.f, osum = 0.f;

        for (int ch = 0; ch < NCHUNK; ch++) {
            const int buf = ch & 1;
            const int u   = ch >> 1;
            mbar_wait(buf ? mbF1 : mbF0, (unsigned)(u & 1));

            const float* pf = ((const float*)(part + (size_t)buf * PART_F2
                                              + tt * PAD2)) + c;
            float a0s = b2c, a1s = 0.f, a2s = 0.f, a3s = 0.f;
            #pragma unroll 4
            for (int j = 0; j < DH; j += 4) {
                a0s += pf[2 * (j + 0)];
                a1s += pf[2 * (j + 1)];
                a2s += pf[2 * (j + 2)];
                a3s += pf[2 * (j + 3)];
            }
            const float s = (a0s + a1s) + (a2s + a3s);

            float r[CHUNK];
            #pragma unroll
            for (int t2 = 0; t2 < CHUNK; t2++)
                r[t2] = __shfl_sync(0xffffffffu, s, t2 * 2 + c);

            mbar_arrive(buf ? mbE1 : mbE0);   // part[buf] free as soon as gathered

            if (lane < 2) {
                float mm = m2, os = osum;
                #pragma unroll
                for (int t2 = 0; t2 < CHUNK; t2++) {
                    mm = fmaf(mm, a2, r[t2]);
                    const float s2v = (mm > 1.0f) ? 1.0f : 0.0f;
                    mm -= s2v;                 // soft reset (thresh2 = 1.0)
                    const int gt = ch * CHUNK + t2;
                    s2p[(size_t)gt * DOUT + lane] = s2v;
                    m2p[(size_t)gt * DOUT + lane] = mm;
                    if (gt > 0) os += mm;
                }
                m2 = mm; osum = os;
            }
        }
        if (lane < 2)
            out_o[b * DOUT + lane] = osum * (1.0f / (float)T_);
    }
}

extern "C" void kernel_launch(void* const* d_in, const int* in_sizes, int n_in,
                              void* d_out, int out_size) {
    const float* x  = (const float*)d_in[0];
    const float* W1 = (const float*)d_in[1];
    const float* b1 = (const float*)d_in[2];
    const float* W2 = (const float*)d_in[3];
    const float* b2 = (const float*)d_in[4];

    const float a1 = (float)exp((double)(-1.0f / 10.0f));
    const float a2 = (float)exp((double)(-1.0f / 20.0f));

    cudaFuncSetAttribute(snn_kernel,
                         cudaFuncAttributeMaxDynamicSharedMemorySize, SMEM_TOTAL);
    snn_kernel<<<B_, NTHR, SMEM_TOTAL>>>(x, W1, b1, W2, b2, (float*)d_out, a1, a2);
}